// round 11
// baseline (speedup 1.0000x reference)
#include <cuda_runtime.h>
#include <cuda_pipeline.h>

#define G  7
#define GG 49            // G*G
#define CH 1470          // 30*GG
#define NB 2             // batches per group
#define STAGES 2
#define THREADS 256

__device__ float        g_accum = 0.0f;
__device__ unsigned int g_count = 0;

__device__ __forceinline__ float warp_sum(float v) {
    #pragma unroll
    for (int o = 16; o > 0; o >>= 1) v += __shfl_down_sync(0xffffffffu, v, o);
    return v;
}

__global__ __launch_bounds__(THREADS) void yolo_loss_kernel(
    const float* __restrict__ pred,
    const float* __restrict__ lab,
    float* __restrict__ out,
    int B, float invB, int nGroups)
{
    __shared__ float s_pred[STAGES][NB * CH];   // 2*11760 B
    __shared__ float s_lab [STAGES][NB * CH];   // 2*11760 B
    __shared__ float warp_sums[8];

    const int tid = threadIdx.x;

    // --- stage loader: stream one group (NB batches) of pred+lab into stage s ---
    auto stage_load = [&](int s, int g) {
        const int nb = min(NB, B - g * NB);
        const long long base = (long long)g * NB * CH;
        if (nb == NB) {
            const float4* gp = (const float4*)(pred + base);
            const float4* gl = (const float4*)(lab  + base);
            float4* sp = (float4*)s_pred[s];
            float4* sl = (float4*)s_lab[s];
            constexpr int N4 = NB * CH / 4;   // 735
            for (int i = tid; i < N4; i += THREADS) {
                __pipeline_memcpy_async(&sp[i], &gp[i], 16);
                __pipeline_memcpy_async(&sl[i], &gl[i], 16);
            }
        } else {
            for (int i = tid; i < nb * CH; i += THREADS) {
                __pipeline_memcpy_async(&s_pred[s][i], &pred[base + i], 4);
                __pipeline_memcpy_async(&s_lab [s][i], &lab [base + i], 4);
            }
        }
    };

    float loss = 0.0f;
    const int stride = gridDim.x;
    int g = blockIdx.x;
    int s = 0;

    if (g < nGroups) {
        stage_load(0, g);
        __pipeline_commit();
    }

    const int bl   = tid / GG;        // local batch 0..NB-1 (valid tid < NB*GG)
    const int cell = tid - bl * GG;
    const float mf = (float)(cell / G);
    const float nf = (float)(cell % G);
    const float invG = 1.0f / (float)G;

    for (; g < nGroups; g += stride) {
        const int gn = g + stride;
        if (gn < nGroups) {
            stage_load(s ^ 1, gn);
            __pipeline_commit();
            __pipeline_wait_prior(1);   // current stage s is complete
        } else {
            __pipeline_wait_prior(0);
        }
        __syncthreads();                // stage s visible to all

        const int nb = min(NB, B - g * NB);
        if (tid < NB * GG && bl < nb) {
            const float* p = s_pred[s] + bl * CH + cell;
            const float* l = s_lab [s] + bl * CH + cell;

            float pv[10];
            #pragma unroll
            for (int c = 0; c < 10; c++) pv[c] = p[c * GG];
            float lv[9];
            #pragma unroll
            for (int c = 0; c < 9; c++) lv[c] = l[c * GG];

            // --- boxes in xyxy ---
            float cx1 = (pv[0] + mf) * invG, cy1 = (pv[1] + nf) * invG;
            float x1a = cx1 - pv[2] * 0.5f, y1a = cy1 - pv[3] * 0.5f;
            float x2a = cx1 + pv[2] * 0.5f, y2a = cy1 + pv[3] * 0.5f;
            float cx2 = (pv[5] + mf) * invG, cy2 = (pv[6] + nf) * invG;
            float x1b = cx2 - pv[7] * 0.5f, y1b = cy2 - pv[8] * 0.5f;
            float x2b = cx2 + pv[7] * 0.5f, y2b = cy2 + pv[8] * 0.5f;
            float cxg = (lv[0] + mf) * invG, cyg = (lv[1] + nf) * invG;
            float x1g = cxg - lv[2] * 0.5f, y1g = cyg - lv[3] * 0.5f;
            float x2g = cxg + lv[2] * 0.5f, y2g = cyg + lv[3] * 0.5f;

            // --- iou(box1, boxg) ---
            float iw1 = fmaxf(fminf(x2a, x2g) - fmaxf(x1a, x1g), 0.0f);
            float ih1 = fmaxf(fminf(y2a, y2g) - fmaxf(y1a, y1g), 0.0f);
            float inter1 = iw1 * ih1;
            float area_a = (x2a - x1a) * (y2a - y1a);
            float area_g = (x2g - x1g) * (y2g - y1g);
            float iou1 = (inter1 > 0.0f) ? inter1 / (area_a + area_g - inter1) : 0.0f;

            // --- iou(box2, boxg) ---
            float iw2 = fmaxf(fminf(x2b, x2g) - fmaxf(x1b, x1g), 0.0f);
            float ih2 = fmaxf(fminf(y2b, y2g) - fmaxf(y1b, y1g), 0.0f);
            float inter2 = iw2 * ih2;
            float area_b = (x2b - x1b) * (y2b - y1b);
            float iou2 = (inter2 > 0.0f) ? inter2 / (area_b + area_g - inter2) : 0.0f;

            bool resp1 = (iou1 >= iou2);

            // --- coord losses ---
            float d0 = pv[0] - lv[0], d1 = pv[1] - lv[1];
            float s2 = sqrtf(pv[2]) - sqrtf(lv[2]);
            float s3 = sqrtf(pv[3]) - sqrtf(lv[3]);
            float coor1 = 5.0f * (d0 * d0 + d1 * d1 + s2 * s2 + s3 * s3);

            float d5 = pv[5] - lv[5], d6 = pv[6] - lv[6];
            float s7 = sqrtf(pv[7]) - sqrtf(lv[7]);
            float s8 = sqrtf(pv[8]) - sqrtf(lv[8]);
            float coor2 = 5.0f * (d5 * d5 + d6 * d6 + s7 * s7 + s8 * s8);

            float e1 = pv[4] - iou1;
            float e2 = pv[9] - iou2;
            float loss_b1 = coor1 + e1 * e1 + 0.5f * e2 * e2;
            float loss_b2 = coor2 + e2 * e2 + 0.5f * e1 * e1;

            // --- class loss (channels 10..29) ---
            float cls = 0.0f;
            #pragma unroll
            for (int c = 10; c < 30; c++) {
                float d = p[c * GG] - l[c * GG];
                cls = fmaf(d, d, cls);
            }

            float obj_loss   = (resp1 ? loss_b1 : loss_b2) + cls;
            float noobj_loss = 0.5f * (pv[4] * pv[4] + pv[9] * pv[9]);

            loss += (lv[4] == 1.0f) ? obj_loss : noobj_loss;
        }
        __syncthreads();   // everyone done reading stage s before it is reloaded
        s ^= 1;
    }

    // --- block reduction ---
    float v = warp_sum(loss);
    int lane = tid & 31;
    int wid  = tid >> 5;
    if (lane == 0) warp_sums[wid] = v;
    __syncthreads();
    if (wid == 0) {
        float bv = (lane < (THREADS >> 5)) ? warp_sums[lane] : 0.0f;
        bv = warp_sum(bv);
        if (lane == 0) {
            atomicAdd(&g_accum, bv);
            __threadfence();
            unsigned int old = atomicInc(&g_count, gridDim.x - 1);
            if (old == gridDim.x - 1) {
                float tot = atomicExch(&g_accum, 0.0f);
                out[0] = tot * invB;
            }
        }
    }
}

extern "C" void kernel_launch(void* const* d_in, const int* in_sizes, int n_in,
                              void* d_out, int out_size) {
    const float* pred = (const float*)d_in[0];
    const float* lab  = (const float*)d_in[1];
    float* out = (float*)d_out;

    int B = in_sizes[0] / CH;           // 32768
    int nGroups = (B + NB - 1) / NB;    // 16384

    int blocks = 148 * 4;               // persistent: 4 blocks/SM (smem-limited)
    if (blocks > nGroups) blocks = nGroups;

    yolo_loss_kernel<<<blocks, THREADS>>>(pred, lab, out, B, 1.0f / (float)B, nGroups);
}

// round 12
// speedup vs baseline: 1.1653x; 1.1653x over previous
#include <cuda_runtime.h>

#define G  7
#define GG 49            // G*G
#define CH 1470          // 30*GG

__device__ float        g_accum = 0.0f;
__device__ unsigned int g_count = 0;

__device__ __forceinline__ float warp_sum(float v) {
    #pragma unroll
    for (int o = 16; o > 0; o >>= 1) v += __shfl_down_sync(0xffffffffu, v, o);
    return v;
}

__global__ __launch_bounds__(256) void yolo_loss_kernel(
    const float* __restrict__ pred,
    const float* __restrict__ lab,
    float* __restrict__ out,
    int total, float invB)
{
    int idx = blockIdx.x * 256 + threadIdx.x;

    float loss = 0.0f;
    if (idx < total) {
        const int b    = idx / GG;
        const int cell = idx - b * GG;
        const int m    = cell / G;     // dim-2 index, pairs with x
        const int n    = cell % G;     // dim-3 index, pairs with y

        const float* p = pred + (long long)b * CH + cell;
        const float* l = lab  + (long long)b * CH + cell;

        // --- always-needed loads (3 independent, in flight together) ---
        float l4 = l[4 * GG];
        float p4 = p[4 * GG];
        float p9 = p[9 * GG];

        const bool obj = (l4 == 1.0f);

        if (obj) {
            // pred channels 0..9 (4 and 9 already loaded)
            float pv[10];
            pv[4] = p4; pv[9] = p9;
            pv[0] = p[0 * GG]; pv[1] = p[1 * GG]; pv[2] = p[2 * GG]; pv[3] = p[3 * GG];
            pv[5] = p[5 * GG]; pv[6] = p[6 * GG]; pv[7] = p[7 * GG]; pv[8] = p[8 * GG];

            // label channels 0..8 (4 already loaded; 9 unused)
            float lv[9];
            lv[4] = l4;
            lv[0] = l[0 * GG]; lv[1] = l[1 * GG]; lv[2] = l[2 * GG]; lv[3] = l[3 * GG];
            lv[5] = l[5 * GG]; lv[6] = l[6 * GG]; lv[7] = l[7 * GG]; lv[8] = l[8 * GG];

            const float mf = (float)m;
            const float nf = (float)n;
            const float invG = 1.0f / (float)G;

            // --- boxes in xyxy ---
            float cx1 = (pv[0] + mf) * invG, cy1 = (pv[1] + nf) * invG;
            float x1a = cx1 - pv[2] * 0.5f, y1a = cy1 - pv[3] * 0.5f;
            float x2a = cx1 + pv[2] * 0.5f, y2a = cy1 + pv[3] * 0.5f;
            float cx2 = (pv[5] + mf) * invG, cy2 = (pv[6] + nf) * invG;
            float x1b = cx2 - pv[7] * 0.5f, y1b = cy2 - pv[8] * 0.5f;
            float x2b = cx2 + pv[7] * 0.5f, y2b = cy2 + pv[8] * 0.5f;
            float cxg = (lv[0] + mf) * invG, cyg = (lv[1] + nf) * invG;
            float x1g = cxg - lv[2] * 0.5f, y1g = cyg - lv[3] * 0.5f;
            float x2g = cxg + lv[2] * 0.5f, y2g = cyg + lv[3] * 0.5f;

            // --- iou(box1, boxg) ---
            float iw1 = fmaxf(fminf(x2a, x2g) - fmaxf(x1a, x1g), 0.0f);
            float ih1 = fmaxf(fminf(y2a, y2g) - fmaxf(y1a, y1g), 0.0f);
            float inter1 = iw1 * ih1;
            float area_a = (x2a - x1a) * (y2a - y1a);
            float area_g = (x2g - x1g) * (y2g - y1g);
            float iou1 = (inter1 > 0.0f) ? inter1 / (area_a + area_g - inter1) : 0.0f;

            // --- iou(box2, boxg) ---
            float iw2 = fmaxf(fminf(x2b, x2g) - fmaxf(x1b, x1g), 0.0f);
            float ih2 = fmaxf(fminf(y2b, y2g) - fmaxf(y1b, y1g), 0.0f);
            float inter2 = iw2 * ih2;
            float area_b = (x2b - x1b) * (y2b - y1b);
            float iou2 = (inter2 > 0.0f) ? inter2 / (area_b + area_g - inter2) : 0.0f;

            bool resp1 = (iou1 >= iou2);

            // --- coord losses ---
            float d0 = pv[0] - lv[0], d1 = pv[1] - lv[1];
            float s2 = sqrtf(pv[2]) - sqrtf(lv[2]);
            float s3 = sqrtf(pv[3]) - sqrtf(lv[3]);
            float coor1 = 5.0f * (d0 * d0 + d1 * d1 + s2 * s2 + s3 * s3);

            float d5 = pv[5] - lv[5], d6 = pv[6] - lv[6];
            float s7 = sqrtf(pv[7]) - sqrtf(lv[7]);
            float s8 = sqrtf(pv[8]) - sqrtf(lv[8]);
            float coor2 = 5.0f * (d5 * d5 + d6 * d6 + s7 * s7 + s8 * s8);

            float e1 = pv[4] - iou1;
            float e2 = pv[9] - iou2;
            float loss_b1 = coor1 + e1 * e1 + 0.5f * e2 * e2;
            float loss_b2 = coor2 + e2 * e2 + 0.5f * e1 * e1;

            // --- class loss (channels 10..29) ---
            float cls = 0.0f;
            #pragma unroll
            for (int c = 10; c < 30; c++) {
                float d = p[c * GG] - l[c * GG];
                cls = fmaf(d, d, cls);
            }

            loss = (resp1 ? loss_b1 : loss_b2) + cls;
        } else {
            loss = 0.5f * (p4 * p4 + p9 * p9);
        }
    }

    // --- block reduction ---
    __shared__ float warp_sums[8];
    float v = warp_sum(loss);
    int lane = threadIdx.x & 31;
    int wid  = threadIdx.x >> 5;
    if (lane == 0) warp_sums[wid] = v;
    __syncthreads();
    if (wid == 0) {
        float bv = (lane < 8) ? warp_sums[lane] : 0.0f;
        bv = warp_sum(bv);
        if (lane == 0) {
            atomicAdd(&g_accum, bv);
            __threadfence();
            unsigned int old = atomicInc(&g_count, gridDim.x - 1);
            if (old == gridDim.x - 1) {
                float tot = atomicExch(&g_accum, 0.0f);
                out[0] = tot * invB;
            }
        }
    }
}

extern "C" void kernel_launch(void* const* d_in, const int* in_sizes, int n_in,
                              void* d_out, int out_size) {
    const float* pred = (const float*)d_in[0];
    const float* lab  = (const float*)d_in[1];
    float* out = (float*)d_out;

    int B = in_sizes[0] / CH;        // 32768
    int total = B * GG;              // 1605632
    int threads = 256;
    int blocks = (total + threads - 1) / threads;

    yolo_loss_kernel<<<blocks, threads>>>(pred, lab, out, total, 1.0f / (float)B);
}